// round 1
// baseline (speedup 1.0000x reference)
#include <cuda_runtime.h>
#include <cuda_bf16.h>

// Problem constants (fixed shapes from reference)
#define T_LEN   4096
#define C_IN    8
#define BATCH   64
#define D_MODEL 128
#define N_STATE 64
#define HID     128
#define CB_ROWS (C_IN*BATCH)    // 512

// GEMM tiling
#define NSPLIT  32
#define TSEG    (T_LEN/NSPLIT)  // 128
#define KC      16
#define RT      64

// Scratch (no allocations allowed -> device globals)
__device__ float g_buf[T_LEN*D_MODEL];                 // g[t][d], 2 MB
__device__ float gs_buf[D_MODEL];                      // Gs[d] = sum_t g[d,t]
__device__ float p_part[NSPLIT*CB_ROWS*D_MODEL];       // k-split partials, 8 MB

// ---------------------------------------------------------------------------
// Kernel 1: g[d,t] = sum_n C[d,n]*B[d,n] * a[d,n]^(T-1-t),  a = sigmoid(log_a)
// One block per (k-chunk of 128, d). Block-uniform skip of underflowed n's.
// Also computes Gs[d] closed-form (geometric series).
// ---------------------------------------------------------------------------
__global__ void decay_kernel(const float* __restrict__ log_a,
                             const float* __restrict__ B_ssm,
                             const float* __restrict__ C_ssm) {
    const int d   = blockIdx.y;
    const int tid = threadIdx.x;

    __shared__ float lna_s[N_STATE];
    __shared__ float cb_s[N_STATE];
    __shared__ float a_s[N_STATE];
    __shared__ float kmax_s[N_STATE];

    if (tid < N_STATE) {
        float la  = log_a[d*N_STATE + tid];
        float a   = 1.f / (1.f + expf(-la));     // sigmoid, accurate
        float lna = logf(a);                     // < 0
        a_s[tid]   = a;
        lna_s[tid] = lna;
        cb_s[tid]  = C_ssm[d*N_STATE + tid] * B_ssm[d*N_STATE + tid];
        // k beyond which a^k underflows (exp(-80) ~ 1.8e-35): exact skip
        kmax_s[tid] = (lna > -1e-6f) ? 1e9f : (-80.f / lna);
    }
    __syncthreads();

    const int   kmin  = blockIdx.x * 128;
    const float kminf = (float)kmin;
    const float kf    = (float)(kmin + tid);

    float acc = 0.f;
    #pragma unroll 4
    for (int n = 0; n < N_STATE; ++n) {
        if (kminf < kmax_s[n]) {                 // block-uniform branch
            acc += cb_s[n] * __expf(kf * lna_s[n]);
        }
    }
    const int t = T_LEN - 1 - (kmin + tid);
    g_buf[t*D_MODEL + d] = acc;

    if (blockIdx.x == 0 && tid == 0) {
        float gs = 0.f;
        for (int n = 0; n < N_STATE; ++n) {
            float aT = __expf((float)T_LEN * lna_s[n]);   // ~0 usually
            gs += cb_s[n] * (1.f - aT) / (1.f - a_s[n]);
        }
        gs_buf[d] = gs;
    }
}

// ---------------------------------------------------------------------------
// Kernel 2: P_part[split] = X[rows, t-seg] @ G[t-seg, D]
// X = in_chan viewed as [512, 4096] row-major. 64x128 block tile, 8x8/thread.
// ---------------------------------------------------------------------------
__global__ void __launch_bounds__(128) gemm_kernel(const float* __restrict__ X) {
    const int split   = blockIdx.x;          // 0..NSPLIT-1
    const int rowbase = blockIdx.y * RT;     // 0..448
    const int tid     = threadIdx.x;         // 0..127

    __shared__ __align__(16) float As[KC][RT];       // [k][row]
    __shared__ __align__(16) float Bs[KC][D_MODEL];  // [k][col]

    float acc[8][8];
    #pragma unroll
    for (int i = 0; i < 8; ++i)
        #pragma unroll
        for (int j = 0; j < 8; ++j) acc[i][j] = 0.f;

    const int r0  = (tid >> 4) * 8;
    const int c0  = (tid & 15) * 8;
    const int ar  = tid >> 1;          // A-load row
    const int ak  = (tid & 1) * 8;     // A-load k offset
    const int bc  = (tid & 31) * 4;    // B-load col
    const int bk0 = tid >> 5;          // B-load k base

    for (int ch = 0; ch < TSEG/KC; ++ch) {
        const int tb = split*TSEG + ch*KC;

        // Load A tile (transposed into As[k][row])
        const float* asrc = X + (rowbase + ar)*T_LEN + tb + ak;
        float4 v0 = *(const float4*)asrc;
        float4 v1 = *(const float4*)(asrc + 4);
        As[ak+0][ar] = v0.x; As[ak+1][ar] = v0.y;
        As[ak+2][ar] = v0.z; As[ak+3][ar] = v0.w;
        As[ak+4][ar] = v1.x; As[ak+5][ar] = v1.y;
        As[ak+6][ar] = v1.z; As[ak+7][ar] = v1.w;

        // Load B tile (coalesced float4)
        #pragma unroll
        for (int it = 0; it < 4; ++it) {
            int kk = it*4 + bk0;
            *(float4*)&Bs[kk][bc] =
                *(const float4*)(g_buf + (tb + kk)*D_MODEL + bc);
        }
        __syncthreads();

        #pragma unroll
        for (int kk = 0; kk < KC; ++kk) {
            float4 a0 = *(const float4*)&As[kk][r0];
            float4 a1 = *(const float4*)&As[kk][r0+4];
            float4 b0 = *(const float4*)&Bs[kk][c0];
            float4 b1 = *(const float4*)&Bs[kk][c0+4];
            float av[8] = {a0.x,a0.y,a0.z,a0.w,a1.x,a1.y,a1.z,a1.w};
            float bv[8] = {b0.x,b0.y,b0.z,b0.w,b1.x,b1.y,b1.z,b1.w};
            #pragma unroll
            for (int i = 0; i < 8; ++i)
                #pragma unroll
                for (int j = 0; j < 8; ++j)
                    acc[i][j] += av[i] * bv[j];
        }
        __syncthreads();
    }

    float* base = p_part + split*CB_ROWS*D_MODEL;
    #pragma unroll
    for (int i = 0; i < 8; ++i) {
        float4 o0 = make_float4(acc[i][0], acc[i][1], acc[i][2], acc[i][3]);
        float4 o1 = make_float4(acc[i][4], acc[i][5], acc[i][6], acc[i][7]);
        float* dst = base + (rowbase + r0 + i)*D_MODEL + c0;
        *(float4*)dst       = o0;
        *(float4*)(dst + 4) = o1;
    }
}

// ---------------------------------------------------------------------------
// Kernel 3: epilogue. One block per batch b, 128 threads (= d = hid index).
// y[b,d] = sum_c m*W_in*P + b_in*Gs + D*(sum_c m^2*W_in + b_in)
// z = gelu_tanh(y) @ W_mu + b_mu ; out[b] = sigmoid(z . W_lin + b_lin)
// ---------------------------------------------------------------------------
__global__ void final_kernel(const float* __restrict__ in_chan,
                             const float* __restrict__ W_in,
                             const float* __restrict__ b_in,
                             const float* __restrict__ D_ssm,
                             const float* __restrict__ W_mu,
                             const float* __restrict__ b_mu,
                             const float* __restrict__ W_lin,
                             const float* __restrict__ b_lin,
                             float* __restrict__ out) {
    const int b   = blockIdx.x;
    const int tid = threadIdx.x;       // d, then hid index

    __shared__ float m_sh[C_IN];
    __shared__ float ysh[D_MODEL];
    __shared__ float red[4];

    if (tid < C_IN)
        m_sh[tid] = in_chan[(tid*BATCH + b)*T_LEN + (T_LEN-1)];
    __syncthreads();

    float bi = b_in[tid];
    float y  = bi * gs_buf[tid];
    float ul = bi;
    #pragma unroll
    for (int c = 0; c < C_IN; ++c) {
        float m = m_sh[c];
        float w = W_in[c*D_MODEL + tid];
        float ps = 0.f;
        const float* pp = p_part + (c*BATCH + b)*D_MODEL + tid;
        #pragma unroll
        for (int s = 0; s < NSPLIT; ++s)
            ps += pp[s*CB_ROWS*D_MODEL];
        y  += m * w * ps;
        ul += m * m * w;
    }
    y += D_ssm[tid] * ul;

    // gelu (tanh approximation, matching jax.nn.gelu default)
    float tg  = 0.7978845608028654f * (y + 0.044715f*y*y*y);
    float gel = 0.5f * y * (1.f + tanhf(tg));
    ysh[tid] = gel;
    __syncthreads();

    float z = b_mu[tid];
    #pragma unroll 8
    for (int dd = 0; dd < D_MODEL; ++dd)
        z += ysh[dd] * W_mu[dd*HID + tid];

    float v = z * W_lin[tid];
    #pragma unroll
    for (int o = 16; o; o >>= 1)
        v += __shfl_down_sync(0xffffffffu, v, o);
    if ((tid & 31) == 0) red[tid >> 5] = v;
    __syncthreads();
    if (tid == 0) {
        float s = red[0] + red[1] + red[2] + red[3] + b_lin[0];
        out[b] = 1.f / (1.f + expf(-s));
    }
}

// ---------------------------------------------------------------------------
extern "C" void kernel_launch(void* const* d_in, const int* in_sizes, int n_in,
                              void* d_out, int out_size) {
    const float* in_chan = (const float*)d_in[0];
    // d_in[1] = h_0, d_in[2] = c_0 : unused (zeros)
    const float* W_in  = (const float*)d_in[3];
    const float* b_in  = (const float*)d_in[4];
    const float* log_a = (const float*)d_in[5];
    const float* B_ssm = (const float*)d_in[6];
    const float* C_ssm = (const float*)d_in[7];
    const float* D_ssm = (const float*)d_in[8];
    const float* W_mu  = (const float*)d_in[9];
    const float* b_mu  = (const float*)d_in[10];
    const float* W_lin = (const float*)d_in[11];
    const float* b_lin = (const float*)d_in[12];
    float* out = (float*)d_out;

    decay_kernel<<<dim3(T_LEN/128, D_MODEL), 128>>>(log_a, B_ssm, C_ssm);
    gemm_kernel <<<dim3(NSPLIT, CB_ROWS/RT), 128>>>(in_chan);
    final_kernel<<<BATCH, D_MODEL>>>(in_chan, W_in, b_in, D_ssm,
                                     W_mu, b_mu, W_lin, b_lin, out);
}

// round 2
// speedup vs baseline: 1.0413x; 1.0413x over previous
#include <cuda_runtime.h>
#include <cuda_bf16.h>

// Problem constants (fixed shapes from reference)
#define T_LEN   4096
#define C_IN    8
#define BATCH   64
#define D_MODEL 128
#define N_STATE 64
#define HID     128
#define CB_ROWS (C_IN*BATCH)    // 512

// GEMM tiling
#define NSPLIT  64
#define TSEG    (T_LEN/NSPLIT)  // 64
#define KC      16
#define RT      64

// Scratch (no allocations allowed -> device globals, zero-initialized by CUDA)
__device__ float g_buf[T_LEN*D_MODEL];                 // g[t][d], 2 MB
__device__ float gs_buf[D_MODEL];                      // Gs[d] = sum_t g[d,t]
__device__ float p_part[NSPLIT*CB_ROWS*D_MODEL];       // k-split partials, 16 MB
__device__ float lna_tab[D_MODEL*N_STATE];             // ln(sigmoid(log_a))
__device__ float cb_tab[D_MODEL*N_STATE];              // C*B
__device__ int   kcut;                                 // max_k with non-negligible a^k
// NOTE: inputs are identical across graph replays, so kcut computed via
// atomicMax w/o reset is the same value every call (monotone, deterministic),
// and regions gated off by kcut keep their zero-init contents = exact values.

// ---------------------------------------------------------------------------
// Kernel 0: per-(d,n) tables + Gs[d] closed form + global kcut.
// grid = D_MODEL blocks, N_STATE threads.
// ---------------------------------------------------------------------------
__global__ void prep_kernel(const float* __restrict__ log_a,
                            const float* __restrict__ B_ssm,
                            const float* __restrict__ C_ssm) {
    const int d = blockIdx.x;
    const int n = threadIdx.x;

    float la  = log_a[d*N_STATE + n];
    float a   = 1.f / (1.f + expf(-la));     // accurate sigmoid
    float lna = logf(a);                     // < 0
    float cb  = C_ssm[d*N_STATE + n] * B_ssm[d*N_STATE + n];
    lna_tab[d*N_STATE + n] = lna;
    cb_tab [d*N_STATE + n] = cb;

    // k beyond which a^k < exp(-80) ~ 1.8e-35 (negligible vs 1e-3 tolerance)
    int km = (lna > -1e-6f) ? T_LEN
                            : min(T_LEN, (int)(-80.f / lna) + 1);

    float aT  = __expf((float)T_LEN * lna);
    float gsn = cb * (1.f - aT) / fmaxf(1.f - a, 1e-30f);

    __shared__ float gs_sh[N_STATE];
    __shared__ int   km_sh[N_STATE];
    gs_sh[n] = gsn;
    km_sh[n] = km;
    __syncthreads();
    if (n == 0) {
        float s = 0.f; int m = 0;
        #pragma unroll
        for (int i = 0; i < N_STATE; ++i) { s += gs_sh[i]; m = max(m, km_sh[i]); }
        gs_buf[d] = s;
        atomicMax(&kcut, m);
    }
}

// ---------------------------------------------------------------------------
// Kernel 1: g[d,t] = sum_n cb[d,n] * a[d,n]^(T-1-t). Blocks with their whole
// k-range beyond kcut exit (g stays zero-init = exact). Tables, no logf.
// grid = (T/128, D_MODEL), 128 threads.
// ---------------------------------------------------------------------------
__global__ void decay_kernel() {
    const int kmin = blockIdx.x * 128;
    if (kmin > kcut) return;

    const int d   = blockIdx.y;
    const int tid = threadIdx.x;

    __shared__ float lna_s[N_STATE];
    __shared__ float cb_s[N_STATE];
    if (tid < N_STATE) {
        lna_s[tid] = lna_tab[d*N_STATE + tid];
        cb_s[tid]  = cb_tab [d*N_STATE + tid];
    }
    __syncthreads();

    const float kminf = (float)kmin;
    const float kf    = (float)(kmin + tid);

    float acc = 0.f;
    #pragma unroll 4
    for (int n = 0; n < N_STATE; ++n) {
        float lna = lna_s[n];
        if (kminf * lna > -80.f) {              // block-uniform per n
            acc += cb_s[n] * __expf(kf * lna);
        }
    }
    const int t = T_LEN - 1 - (kmin + tid);
    g_buf[t*D_MODEL + d] = acc;
}

// ---------------------------------------------------------------------------
// Kernel 2: P_part[split] = X[rows, t-seg] @ G[t-seg, D]
// X = in_chan viewed as [512, 4096] row-major. 64x128 block tile, 8x8/thread.
// Splits whose k-range is entirely > kcut exit (p_part stays zero, and the
// epilogue skips them anyway).
// ---------------------------------------------------------------------------
__global__ void __launch_bounds__(128) gemm_kernel(const float* __restrict__ X) {
    const int split = blockIdx.x;            // 0..NSPLIT-1 over t
    if (T_LEN - TSEG*(split+1) > kcut) return;   // min k of this split > kcut

    const int rowbase = blockIdx.y * RT;     // 0..448
    const int tid     = threadIdx.x;         // 0..127

    __shared__ __align__(16) float As[KC][RT];       // [k][row]
    __shared__ __align__(16) float Bs[KC][D_MODEL];  // [k][col]

    float acc[8][8];
    #pragma unroll
    for (int i = 0; i < 8; ++i)
        #pragma unroll
        for (int j = 0; j < 8; ++j) acc[i][j] = 0.f;

    const int r0  = (tid >> 4) * 8;
    const int c0  = (tid & 15) * 8;
    const int ar  = tid >> 1;          // A-load row
    const int ak  = (tid & 1) * 8;     // A-load k offset
    const int bc  = (tid & 31) * 4;    // B-load col
    const int bk0 = tid >> 5;          // B-load k base

    #pragma unroll
    for (int ch = 0; ch < TSEG/KC; ++ch) {
        const int tb = split*TSEG + ch*KC;

        // Load A tile (transposed into As[k][row])
        const float* asrc = X + (rowbase + ar)*T_LEN + tb + ak;
        float4 v0 = *(const float4*)asrc;
        float4 v1 = *(const float4*)(asrc + 4);
        As[ak+0][ar] = v0.x; As[ak+1][ar] = v0.y;
        As[ak+2][ar] = v0.z; As[ak+3][ar] = v0.w;
        As[ak+4][ar] = v1.x; As[ak+5][ar] = v1.y;
        As[ak+6][ar] = v1.z; As[ak+7][ar] = v1.w;

        // Load B tile (coalesced float4)
        #pragma unroll
        for (int it = 0; it < 4; ++it) {
            int kk = it*4 + bk0;
            *(float4*)&Bs[kk][bc] =
                *(const float4*)(g_buf + (tb + kk)*D_MODEL + bc);
        }
        __syncthreads();

        #pragma unroll
        for (int kk = 0; kk < KC; ++kk) {
            float4 a0 = *(const float4*)&As[kk][r0];
            float4 a1 = *(const float4*)&As[kk][r0+4];
            float4 b0 = *(const float4*)&Bs[kk][c0];
            float4 b1 = *(const float4*)&Bs[kk][c0+4];
            float av[8] = {a0.x,a0.y,a0.z,a0.w,a1.x,a1.y,a1.z,a1.w};
            float bv[8] = {b0.x,b0.y,b0.z,b0.w,b1.x,b1.y,b1.z,b1.w};
            #pragma unroll
            for (int i = 0; i < 8; ++i)
                #pragma unroll
                for (int j = 0; j < 8; ++j)
                    acc[i][j] += av[i] * bv[j];
        }
        __syncthreads();
    }

    float* base = p_part + split*CB_ROWS*D_MODEL;
    #pragma unroll
    for (int i = 0; i < 8; ++i) {
        float4 o0 = make_float4(acc[i][0], acc[i][1], acc[i][2], acc[i][3]);
        float4 o1 = make_float4(acc[i][4], acc[i][5], acc[i][6], acc[i][7]);
        float* dst = base + (rowbase + r0 + i)*D_MODEL + c0;
        *(float4*)dst       = o0;
        *(float4*)(dst + 4) = o1;
    }
}

// ---------------------------------------------------------------------------
// Kernel 3: epilogue. One block per batch b, 128 threads (= d = hid index).
// y[b,d] = sum_c m*W_in*P + b_in*Gs + D*(sum_c m^2*W_in + b_in)
// z = gelu_tanh(y) @ W_mu + b_mu ; out[b] = sigmoid(z . W_lin + b_lin)
// ---------------------------------------------------------------------------
__global__ void final_kernel(const float* __restrict__ in_chan,
                             const float* __restrict__ W_in,
                             const float* __restrict__ b_in,
                             const float* __restrict__ D_ssm,
                             const float* __restrict__ W_mu,
                             const float* __restrict__ b_mu,
                             const float* __restrict__ W_lin,
                             const float* __restrict__ b_lin,
                             float* __restrict__ out) {
    const int b   = blockIdx.x;
    const int tid = threadIdx.x;       // d, then hid index

    __shared__ float m_sh[C_IN];
    __shared__ float ysh[D_MODEL];
    __shared__ float red[4];

    if (tid < C_IN)
        m_sh[tid] = in_chan[(tid*BATCH + b)*T_LEN + (T_LEN-1)];
    __syncthreads();

    // Sum k-split partials, skipping splits gated off by kcut (their
    // p_part is zero anyway; skipping saves ~60% of the loads).
    const int kc = kcut;
    float ps[C_IN];
    #pragma unroll
    for (int c = 0; c < C_IN; ++c) ps[c] = 0.f;
    for (int s = 0; s < NSPLIT; ++s) {
        if (T_LEN - TSEG*(s+1) <= kc) {
            const float* pp = p_part + (s*CB_ROWS + b)*D_MODEL + tid;
            #pragma unroll
            for (int c = 0; c < C_IN; ++c)
                ps[c] += pp[c*BATCH*D_MODEL];
        }
    }

    float bi = b_in[tid];
    float y  = bi * gs_buf[tid];
    float ul = bi;
    #pragma unroll
    for (int c = 0; c < C_IN; ++c) {
        float m = m_sh[c];
        float w = W_in[c*D_MODEL + tid];
        y  += m * w * ps[c];
        ul += m * m * w;
    }
    y += D_ssm[tid] * ul;

    // gelu (tanh approximation, matching jax.nn.gelu default)
    float tg  = 0.7978845608028654f * (y + 0.044715f*y*y*y);
    float gel = 0.5f * y * (1.f + tanhf(tg));
    ysh[tid] = gel;
    __syncthreads();

    float z = b_mu[tid];
    #pragma unroll 8
    for (int dd = 0; dd < D_MODEL; ++dd)
        z += ysh[dd] * W_mu[dd*HID + tid];

    float v = z * W_lin[tid];
    #pragma unroll
    for (int o = 16; o; o >>= 1)
        v += __shfl_down_sync(0xffffffffu, v, o);
    if ((tid & 31) == 0) red[tid >> 5] = v;
    __syncthreads();
    if (tid == 0) {
        float s = red[0] + red[1] + red[2] + red[3] + b_lin[0];
        out[b] = 1.f / (1.f + expf(-s));
    }
}

// ---------------------------------------------------------------------------
extern "C" void kernel_launch(void* const* d_in, const int* in_sizes, int n_in,
                              void* d_out, int out_size) {
    const float* in_chan = (const float*)d_in[0];
    // d_in[1] = h_0, d_in[2] = c_0 : unused (zeros)
    const float* W_in  = (const float*)d_in[3];
    const float* b_in  = (const float*)d_in[4];
    const float* log_a = (const float*)d_in[5];
    const float* B_ssm = (const float*)d_in[6];
    const float* C_ssm = (const float*)d_in[7];
    const float* D_ssm = (const float*)d_in[8];
    const float* W_mu  = (const float*)d_in[9];
    const float* b_mu  = (const float*)d_in[10];
    const float* W_lin = (const float*)d_in[11];
    const float* b_lin = (const float*)d_in[12];
    float* out = (float*)d_out;

    prep_kernel <<<D_MODEL, N_STATE>>>(log_a, B_ssm, C_ssm);
    decay_kernel<<<dim3(T_LEN/128, D_MODEL), 128>>>();
    gemm_kernel <<<dim3(NSPLIT, CB_ROWS/RT), 128>>>(in_chan);
    final_kernel<<<BATCH, D_MODEL>>>(in_chan, W_in, b_in, D_ssm,
                                     W_mu, b_mu, W_lin, b_lin, out);
}

// round 3
// speedup vs baseline: 1.6314x; 1.5667x over previous
#include <cuda_runtime.h>
#include <cuda_bf16.h>

// Problem constants (fixed shapes from reference)
#define T_LEN   4096
#define C_IN    8
#define BATCH   64
#define D_MODEL 128
#define N_STATE 64
#define HID     128
#define CB_ROWS (C_IN*BATCH)    // 512

// Decay negligibility threshold: terms with a^k < e^-THRESH are dropped.
// Tail bound: e^-34/(1-a_max) * |cb| * |u| * 64  ~ 1e-10 on y ~ O(1),
// far below both the 1e-3 tolerance and fp32 accumulation noise.
#define THRESH  34.0f

// GEMM tiling
#define NSPLIT  64
#define TSEG    (T_LEN/NSPLIT)  // 64
#define KC      16
#define RT      64

// Scratch (no allocations allowed -> device globals, zero-initialized once)
__device__ float g_buf[T_LEN*D_MODEL];                 // g[t][d], 2 MB
__device__ float gs_buf[D_MODEL];                      // Gs[d]
__device__ float p_part[NSPLIT*CB_ROWS*D_MODEL];       // k-split partials
__device__ float P_buf[CB_ROWS*D_MODEL];               // reduced P, 256 KB
__device__ float lna_tab[D_MODEL*N_STATE];             // ln(sigmoid(log_a))
__device__ float cb_tab[D_MODEL*N_STATE];              // C*B
__device__ int   kcut;                                 // max non-negligible k
// kcut via atomicMax w/o reset: inputs constant across graph replays ->
// monotone & identical every call (deterministic).

__device__ __forceinline__ int split_lo(int kc) {
    // smallest split s whose k-range [T-TSEG*(s+1), T-TSEG*s) intersects k<=kc
    int s0 = (T_LEN - kc + TSEG - 1) / TSEG - 1;
    return s0 < 0 ? 0 : s0;
}

// ---------------------------------------------------------------------------
// Kernel 0: tables + Gs[d] (exact geometric series) + global kcut.
// ---------------------------------------------------------------------------
__global__ void prep_kernel(const float* __restrict__ log_a,
                            const float* __restrict__ B_ssm,
                            const float* __restrict__ C_ssm) {
    const int d = blockIdx.x;
    const int n = threadIdx.x;

    float la  = log_a[d*N_STATE + n];
    float a   = 1.f / (1.f + expf(-la));     // accurate sigmoid
    float lna = logf(a);                     // < 0
    float cb  = C_ssm[d*N_STATE + n] * B_ssm[d*N_STATE + n];
    lna_tab[d*N_STATE + n] = lna;
    cb_tab [d*N_STATE + n] = cb;

    int km = (lna > -1e-6f) ? T_LEN
                            : min(T_LEN, (int)(THRESH / -lna) + 1);

    float aT  = __expf((float)T_LEN * lna);
    float gsn = cb * (1.f - aT) / fmaxf(1.f - a, 1e-30f);

    __shared__ float gs_sh[N_STATE];
    __shared__ int   km_sh[N_STATE];
    gs_sh[n] = gsn;
    km_sh[n] = km;
    __syncthreads();
    if (n == 0) {
        float s = 0.f; int m = 0;
        #pragma unroll
        for (int i = 0; i < N_STATE; ++i) { s += gs_sh[i]; m = max(m, km_sh[i]); }
        gs_buf[d] = s;
        atomicMax(&kcut, m);
    }
}

// ---------------------------------------------------------------------------
// Kernel 1: g[d,t] = sum_n cb * a^(T-1-t). Chunks beyond kcut never written:
// their zero-init content IS the (negligible->0) correct value.
// ---------------------------------------------------------------------------
__global__ void decay_kernel() {
    const int kmin = blockIdx.x * 128;
    if (kmin > kcut) return;

    const int d   = blockIdx.y;
    const int tid = threadIdx.x;

    __shared__ float lna_s[N_STATE];
    __shared__ float cb_s[N_STATE];
    if (tid < N_STATE) {
        lna_s[tid] = lna_tab[d*N_STATE + tid];
        cb_s[tid]  = cb_tab [d*N_STATE + tid];
    }
    __syncthreads();

    const float kminf = (float)kmin;
    const float kf    = (float)(kmin + tid);

    float acc = 0.f;
    #pragma unroll 4
    for (int n = 0; n < N_STATE; ++n) {
        float lna = lna_s[n];
        if (kminf * lna > -THRESH) {            // block-uniform per n
            acc += cb_s[n] * __expf(kf * lna);
        }
    }
    const int t = T_LEN - 1 - (kmin + tid);
    g_buf[t*D_MODEL + d] = acc;
}

// ---------------------------------------------------------------------------
// Kernel 2: P_part[s] = X[rows, t-seg(s)] @ G[t-seg(s), D]
// X = in_chan viewed as [512, 4096]. 64x128 block tile, 8x8 per thread.
// Splits below split_lo exit before doing any work.
// ---------------------------------------------------------------------------
__global__ void __launch_bounds__(128) gemm_kernel(const float* __restrict__ X) {
    const int split = blockIdx.x;
    if (split < split_lo(kcut)) return;

    const int rowbase = blockIdx.y * RT;
    const int tid     = threadIdx.x;

    __shared__ __align__(16) float As[KC][RT];
    __shared__ __align__(16) float Bs[KC][D_MODEL];

    float acc[8][8];
    #pragma unroll
    for (int i = 0; i < 8; ++i)
        #pragma unroll
        for (int j = 0; j < 8; ++j) acc[i][j] = 0.f;

    const int r0  = (tid >> 4) * 8;
    const int c0  = (tid & 15) * 8;
    const int ar  = tid >> 1;
    const int ak  = (tid & 1) * 8;
    const int bc  = (tid & 31) * 4;
    const int bk0 = tid >> 5;

    #pragma unroll
    for (int ch = 0; ch < TSEG/KC; ++ch) {
        const int tb = split*TSEG + ch*KC;

        const float* asrc = X + (rowbase + ar)*T_LEN + tb + ak;
        float4 v0 = *(const float4*)asrc;
        float4 v1 = *(const float4*)(asrc + 4);
        As[ak+0][ar] = v0.x; As[ak+1][ar] = v0.y;
        As[ak+2][ar] = v0.z; As[ak+3][ar] = v0.w;
        As[ak+4][ar] = v1.x; As[ak+5][ar] = v1.y;
        As[ak+6][ar] = v1.z; As[ak+7][ar] = v1.w;

        #pragma unroll
        for (int it = 0; it < 4; ++it) {
            int kk = it*4 + bk0;
            *(float4*)&Bs[kk][bc] =
                *(const float4*)(g_buf + (tb + kk)*D_MODEL + bc);
        }
        __syncthreads();

        #pragma unroll
        for (int kk = 0; kk < KC; ++kk) {
            float4 a0 = *(const float4*)&As[kk][r0];
            float4 a1 = *(const float4*)&As[kk][r0+4];
            float4 b0 = *(const float4*)&Bs[kk][c0];
            float4 b1 = *(const float4*)&Bs[kk][c0+4];
            float av[8] = {a0.x,a0.y,a0.z,a0.w,a1.x,a1.y,a1.z,a1.w};
            float bv[8] = {b0.x,b0.y,b0.z,b0.w,b1.x,b1.y,b1.z,b1.w};
            #pragma unroll
            for (int i = 0; i < 8; ++i)
                #pragma unroll
                for (int j = 0; j < 8; ++j)
                    acc[i][j] += av[i] * bv[j];
        }
        __syncthreads();
    }

    float* base = p_part + split*CB_ROWS*D_MODEL;
    #pragma unroll
    for (int i = 0; i < 8; ++i) {
        float4 o0 = make_float4(acc[i][0], acc[i][1], acc[i][2], acc[i][3]);
        float4 o1 = make_float4(acc[i][4], acc[i][5], acc[i][6], acc[i][7]);
        float* dst = base + (rowbase + r0 + i)*D_MODEL + c0;
        *(float4*)dst       = o0;
        *(float4*)(dst + 4) = o1;
    }
}

// ---------------------------------------------------------------------------
// Kernel 3: reduce active split partials -> P_buf [512][128].
// 16384 float4-threads, fully coalesced, all traffic L2-resident.
// ---------------------------------------------------------------------------
__global__ void reduce_kernel() {
    const int idx = blockIdx.x * blockDim.x + threadIdx.x;  // float4 index
    const int s0  = split_lo(kcut);

    float4 acc = make_float4(0.f, 0.f, 0.f, 0.f);
    const float4* pp = (const float4*)p_part;
    for (int s = s0; s < NSPLIT; ++s) {
        float4 v = pp[s*(CB_ROWS*D_MODEL/4) + idx];
        acc.x += v.x; acc.y += v.y; acc.z += v.z; acc.w += v.w;
    }
    ((float4*)P_buf)[idx] = acc;
}

// ---------------------------------------------------------------------------
// Kernel 4: epilogue. One block per batch b, 128 threads.
// ---------------------------------------------------------------------------
__global__ void final_kernel(const float* __restrict__ in_chan,
                             const float* __restrict__ W_in,
                             const float* __restrict__ b_in,
                             const float* __restrict__ D_ssm,
                             const float* __restrict__ W_mu,
                             const float* __restrict__ b_mu,
                             const float* __restrict__ W_lin,
                             const float* __restrict__ b_lin,
                             float* __restrict__ out) {
    const int b   = blockIdx.x;
    const int tid = threadIdx.x;

    __shared__ float m_sh[C_IN];
    __shared__ float ysh[D_MODEL];
    __shared__ float red[4];

    if (tid < C_IN)
        m_sh[tid] = in_chan[(tid*BATCH + b)*T_LEN + (T_LEN-1)];
    __syncthreads();

    float bi = b_in[tid];
    float y  = bi * gs_buf[tid];
    float ul = bi;
    #pragma unroll
    for (int c = 0; c < C_IN; ++c) {
        float m = m_sh[c];
        float w = W_in[c*D_MODEL + tid];
        float p = P_buf[(c*BATCH + b)*D_MODEL + tid];
        y  += m * w * p;
        ul += m * m * w;
    }
    y += D_ssm[tid] * ul;

    // gelu (tanh approximation, matching jax.nn.gelu default)
    float tg  = 0.7978845608028654f * (y + 0.044715f*y*y*y);
    float gel = 0.5f * y * (1.f + tanhf(tg));
    ysh[tid] = gel;
    __syncthreads();

    float z = b_mu[tid];
    #pragma unroll 8
    for (int dd = 0; dd < D_MODEL; ++dd)
        z += ysh[dd] * W_mu[dd*HID + tid];

    float v = z * W_lin[tid];
    #pragma unroll
    for (int o = 16; o; o >>= 1)
        v += __shfl_down_sync(0xffffffffu, v, o);
    if ((tid & 31) == 0) red[tid >> 5] = v;
    __syncthreads();
    if (tid == 0) {
        float s = red[0] + red[1] + red[2] + red[3] + b_lin[0];
        out[b] = 1.f / (1.f + expf(-s));
    }
}

// ---------------------------------------------------------------------------
extern "C" void kernel_launch(void* const* d_in, const int* in_sizes, int n_in,
                              void* d_out, int out_size) {
    const float* in_chan = (const float*)d_in[0];
    // d_in[1] = h_0, d_in[2] = c_0 : unused (zeros)
    const float* W_in  = (const float*)d_in[3];
    const float* b_in  = (const float*)d_in[4];
    const float* log_a = (const float*)d_in[5];
    const float* B_ssm = (const float*)d_in[6];
    const float* C_ssm = (const float*)d_in[7];
    const float* D_ssm = (const float*)d_in[8];
    const float* W_mu  = (const float*)d_in[9];
    const float* b_mu  = (const float*)d_in[10];
    const float* W_lin = (const float*)d_in[11];
    const float* b_lin = (const float*)d_in[12];
    float* out = (float*)d_out;

    prep_kernel  <<<D_MODEL, N_STATE>>>(log_a, B_ssm, C_ssm);
    decay_kernel <<<dim3(T_LEN/128, D_MODEL), 128>>>();
    gemm_kernel  <<<dim3(NSPLIT, CB_ROWS/RT), 128>>>(in_chan);
    reduce_kernel<<<CB_ROWS*D_MODEL/4/128, 128>>>();
    final_kernel <<<BATCH, D_MODEL>>>(in_chan, W_in, b_in, D_ssm,
                                      W_mu, b_mu, W_lin, b_lin, out);
}